// round 1
// baseline (speedup 1.0000x reference)
#include <cuda_runtime.h>

// ---------------------------------------------------------------------------
// SingleWindowZigZagAttention: B=256 windows, N=256 tokens, DIM=512, H=16, HD=32
// Pipeline:
//   1) sgemm<0>: X(65536x512) @ qkv_w(512x1536) + qkv_b, scatter to g_q/g_k/g_v
//      in (b,h,n,d) layout; q pre-scaled by HD^-0.5.
//   2) attn_kernel: one block per (b,h). K/V tiles resident in smem, per-head
//      bias row in smem, zigzag coords rebuilt in-kernel. One query row per
//      thread, online softmax. Output written in (b,n,DIM) layout to g_attn.
//   3) sgemm<1>: g_attn(65536x512) @ proj_w(512x512) + proj_b -> d_out.
// ---------------------------------------------------------------------------

#define WSZ   16
#define NT    256          // tokens per window
#define BW    256          // windows
#define DIMM  512
#define NH    16
#define HDIM  32
#define QSCALE 0.17677669529663687f   // 32^-0.5

// Scratch (no allocations allowed -> device globals)
__device__ float g_q[(size_t)BW * NH * NT * HDIM];     // 134 MB
__device__ float g_k[(size_t)BW * NH * NT * HDIM];     // 134 MB
__device__ float g_v[(size_t)BW * NH * NT * HDIM];     // 134 MB
__device__ float g_attn[(size_t)BW * NT * DIMM];       // 134 MB

// ---------------------------------------------------------------------------
// Classic 128x128x8 fp32 SGEMM, 256 threads, 8x8 microtile per thread.
// MODE 0: A = inputs, epilogue scatters QKV (adds qkv_b, scales q).
// MODE 1: A = g_attn, epilogue adds proj_b and writes C (=d_out).
// M is implicit 65536 (grid.y * 128). K divisible by 8, Nn by 128.
// ---------------------------------------------------------------------------
template <int MODE>
__global__ __launch_bounds__(256) void sgemm_kernel(
    const float* __restrict__ A, const float* __restrict__ Bm,
    const float* __restrict__ bias, float* __restrict__ C,
    int K, int Nn)
{
    __shared__ float As[8][128];
    __shared__ float Bs[8][128];

    const float* Ap = (MODE == 1) ? (const float*)g_attn : A;

    const int t = threadIdx.x;
    const int rowBase = blockIdx.y * 128;
    const int colBase = blockIdx.x * 128;

    const int a_row = t >> 1;            // 0..127
    const int a_c4  = (t & 1) * 4;       // 0 or 4
    const int b_row = t >> 5;            // 0..7
    const int b_c4  = (t & 31) * 4;      // 0..124

    const float* Aptr = Ap + (size_t)(rowBase + a_row) * K + a_c4;
    const float* Bptr = Bm + (size_t)b_row * Nn + colBase + b_c4;

    const int ty = t >> 4;               // 0..15
    const int tx = t & 15;               // 0..15

    float acc[8][8];
#pragma unroll
    for (int i = 0; i < 8; i++)
#pragma unroll
        for (int j = 0; j < 8; j++) acc[i][j] = 0.f;

    for (int k0 = 0; k0 < K; k0 += 8) {
        float4 av = *(const float4*)(Aptr + k0);
        As[a_c4 + 0][a_row] = av.x;
        As[a_c4 + 1][a_row] = av.y;
        As[a_c4 + 2][a_row] = av.z;
        As[a_c4 + 3][a_row] = av.w;
        float4 bv = *(const float4*)(Bptr + (size_t)k0 * Nn);
        *(float4*)&Bs[b_row][b_c4] = bv;
        __syncthreads();

#pragma unroll
        for (int kk = 0; kk < 8; kk++) {
            float ar[8], br[8];
            *(float4*)(ar + 0) = *(const float4*)&As[kk][ty * 8 + 0];
            *(float4*)(ar + 4) = *(const float4*)&As[kk][ty * 8 + 4];
            *(float4*)(br + 0) = *(const float4*)&Bs[kk][tx * 8 + 0];
            *(float4*)(br + 4) = *(const float4*)&Bs[kk][tx * 8 + 4];
#pragma unroll
            for (int i = 0; i < 8; i++)
#pragma unroll
                for (int j = 0; j < 8; j++)
                    acc[i][j] += ar[i] * br[j];
        }
        __syncthreads();
    }

    // Epilogue
#pragma unroll
    for (int i = 0; i < 8; i++) {
        const int row = rowBase + ty * 8 + i;
#pragma unroll
        for (int j = 0; j < 8; j++) {
            const int col = colBase + tx * 8 + j;
            float v = acc[i][j] + bias[col];
            if (MODE == 0) {
                const int b  = row >> 8;           // window
                const int n  = row & 255;          // token
                const int sel = col >> 9;          // 0:q 1:k 2:v
                const int h  = (col >> 5) & (NH - 1);
                const int hd = col & (HDIM - 1);
                const int off = ((b * NH + h) * NT + n) * HDIM + hd;
                if (sel == 0)      g_q[off] = v * QSCALE;
                else if (sel == 1) g_k[off] = v;
                else               g_v[off] = v;
            } else {
                C[(size_t)row * Nn + col] = v;
            }
        }
    }
}

// ---------------------------------------------------------------------------
// Attention: one block per (b,h). 256 threads, one query row each.
// Dynamic smem: Ks[256*32] | Vs[256*32] | biash[961] | rc[256] | cc[256]
// ---------------------------------------------------------------------------
#define SM_V_OFF   (NT * HDIM)            // 8192 floats
#define SM_B_OFF   (2 * NT * HDIM)        // 16384 floats
#define SM_RC_OFF  (SM_B_OFF + 961)       // 17345 floats (int region)
#define SM_CC_OFF  (SM_RC_OFF + NT)       // 17601
#define ATTN_SMEM_FLOATS (SM_CC_OFF + NT) // 17857
#define ATTN_SMEM_BYTES  (ATTN_SMEM_FLOATS * 4)

__global__ __launch_bounds__(256) void attn_kernel(const float* __restrict__ bias_table)
{
    extern __shared__ float smem[];
    float* Ks    = smem;
    float* Vs    = smem + SM_V_OFF;
    float* biash = smem + SM_B_OFF;
    int*   rc    = (int*)(smem + SM_RC_OFF);
    int*   cc    = (int*)(smem + SM_CC_OFF);

    const int bh = blockIdx.x;
    const int b  = bh >> 4;
    const int h  = bh & (NH - 1);
    const int t  = threadIdx.x;

    const float4* Kg4 = (const float4*)(g_k + (size_t)bh * NT * HDIM);
    const float4* Vg4 = (const float4*)(g_v + (size_t)bh * NT * HDIM);
    float4* Ks4 = (float4*)Ks;
    float4* Vs4 = (float4*)Vs;
#pragma unroll
    for (int i = t; i < NT * HDIM / 4; i += 256) {
        Ks4[i] = Kg4[i];
        Vs4[i] = Vg4[i];
    }
    for (int i = t; i < 961; i += 256) biash[i] = bias_table[i * NH + h];

    if (t == 0) {
        int r = 0, c = 0;
        for (int n = 0; n < NT; n++) {
            rc[n] = r; cc[n] = c;
            if (((r + c) & 1) == 0) {
                if (c == WSZ - 1) r++;
                else if (r == 0) c++;
                else { r--; c++; }
            } else {
                if (r == WSZ - 1) c++;
                else if (c == 0) r++;
                else { r++; c--; }
            }
        }
    }
    __syncthreads();

    // Load my query row (pre-scaled in GEMM epilogue)
    float q[HDIM];
    const float4* Qg4 = (const float4*)(g_q + ((size_t)bh * NT + t) * HDIM);
#pragma unroll
    for (int i = 0; i < HDIM / 4; i++) {
        float4 v = Qg4[i];
        q[4 * i + 0] = v.x; q[4 * i + 1] = v.y;
        q[4 * i + 2] = v.z; q[4 * i + 3] = v.w;
    }
    const int rn = rc[t], cn = cc[t];

    float mrun = -1e30f, l = 0.f;
    float acc[HDIM];
#pragma unroll
    for (int d = 0; d < HDIM; d++) acc[d] = 0.f;

    for (int m = 0; m < NT; m++) {
        const float* kr = &Ks[m * HDIM];
        float dot = 0.f;
#pragma unroll
        for (int d = 0; d < HDIM; d++) dot += q[d] * kr[d];
        const int dr = rn - rc[m] + (WSZ - 1);
        const int dc = cn - cc[m] + (WSZ - 1);
        const float s = dot + biash[dr * (2 * WSZ - 1) + dc];

        if (s > mrun) {
            const float corr = __expf(mrun - s);
            l *= corr;
#pragma unroll
            for (int d = 0; d < HDIM; d++) acc[d] *= corr;
            mrun = s;
        }
        const float p = __expf(s - mrun);
        l += p;
        const float* vr = &Vs[m * HDIM];
#pragma unroll
        for (int d = 0; d < HDIM; d++) acc[d] += p * vr[d];
    }

    const float inv = 1.f / l;
    float* outp = g_attn + ((size_t)(b * NT + t)) * DIMM + h * HDIM;
#pragma unroll
    for (int d = 0; d < HDIM; d++) outp[d] = acc[d] * inv;
}

// ---------------------------------------------------------------------------
// Launch
// ---------------------------------------------------------------------------
extern "C" void kernel_launch(void* const* d_in, const int* in_sizes, int n_in,
                              void* d_out, int out_size)
{
    const float* inputs     = (const float*)d_in[0];  // (256,256,512)
    const float* qkv_w      = (const float*)d_in[1];  // (512,1536)
    const float* qkv_b      = (const float*)d_in[2];  // (1536,)
    const float* proj_w     = (const float*)d_in[3];  // (512,512)
    const float* proj_b     = (const float*)d_in[4];  // (512,)
    const float* bias_table = (const float*)d_in[5];  // (961,16)
    float* out = (float*)d_out;                       // (256,256,512)

    // 1) QKV projection + scatter
    {
        dim3 grid(1536 / 128, (BW * NT) / 128);   // 12 x 512
        sgemm_kernel<0><<<grid, 256>>>(inputs, qkv_w, qkv_b, nullptr, DIMM, 3 * DIMM);
    }

    // 2) Attention
    {
        cudaFuncSetAttribute(attn_kernel, cudaFuncAttributeMaxDynamicSharedMemorySize,
                             ATTN_SMEM_BYTES);
        attn_kernel<<<BW * NH, 256, ATTN_SMEM_BYTES>>>(bias_table);
    }

    // 3) Output projection
    {
        dim3 grid(DIMM / 128, (BW * NT) / 128);   // 4 x 512
        sgemm_kernel<1><<<grid, 256>>>(nullptr, proj_w, proj_b, out, DIMM, DIMM);
    }
}

// round 3
// speedup vs baseline: 1.0017x; 1.0017x over previous
#include <cuda_runtime.h>

// ---------------------------------------------------------------------------
// SingleWindowZigZagAttention: B=256 windows, N=256 tokens, DIM=512, H=16, HD=32
// Pipeline:
//   1) sgemm<0>: X(65536x512) @ qkv_w(512x1536) + qkv_b, scatter to g_q/g_k/g_v
//      in (b,h,n,d) layout; q pre-scaled by HD^-0.5.
//   2) attn_kernel: one block per (b,h). K/V tiles resident in smem, per-head
//      bias row in smem, zigzag coords rebuilt in-kernel. One query row per
//      thread, online softmax. Output written in (b,n,DIM) layout to g_attn.
//   3) sgemm<1>: g_attn(65536x512) @ proj_w(512x512) + proj_b -> d_out.
// ---------------------------------------------------------------------------

#define WSZ   16
#define NT    256          // tokens per window
#define BW    256          // windows
#define DIMM  512
#define NH    16
#define HDIM  32
#define QSCALE 0.17677669529663687f   // 32^-0.5

// Scratch (no allocations allowed -> device globals)
__device__ float g_q[(size_t)BW * NH * NT * HDIM];     // 134 MB
__device__ float g_k[(size_t)BW * NH * NT * HDIM];     // 134 MB
__device__ float g_v[(size_t)BW * NH * NT * HDIM];     // 134 MB
__device__ float g_attn[(size_t)BW * NT * DIMM];       // 134 MB

// ---------------------------------------------------------------------------
// Classic 128x128x8 fp32 SGEMM, 256 threads, 8x8 microtile per thread.
// MODE 0: A = inputs, epilogue scatters QKV (adds qkv_b, scales q).
// MODE 1: A = g_attn, epilogue adds proj_b and writes C (=d_out).
// M is implicit 65536 (grid.y * 128). K divisible by 8, Nn by 128.
// ---------------------------------------------------------------------------
template <int MODE>
__global__ __launch_bounds__(256) void sgemm_kernel(
    const float* __restrict__ A, const float* __restrict__ Bm,
    const float* __restrict__ bias, float* __restrict__ C,
    int K, int Nn)
{
    __shared__ float As[8][128];
    __shared__ float Bs[8][128];

    const float* Ap = (MODE == 1) ? (const float*)g_attn : A;

    const int t = threadIdx.x;
    const int rowBase = blockIdx.y * 128;
    const int colBase = blockIdx.x * 128;

    const int a_row = t >> 1;            // 0..127
    const int a_c4  = (t & 1) * 4;       // 0 or 4
    const int b_row = t >> 5;            // 0..7
    const int b_c4  = (t & 31) * 4;      // 0..124

    const float* Aptr = Ap + (size_t)(rowBase + a_row) * K + a_c4;
    const float* Bptr = Bm + (size_t)b_row * Nn + colBase + b_c4;

    const int ty = t >> 4;               // 0..15
    const int tx = t & 15;               // 0..15

    float acc[8][8];
#pragma unroll
    for (int i = 0; i < 8; i++)
#pragma unroll
        for (int j = 0; j < 8; j++) acc[i][j] = 0.f;

    for (int k0 = 0; k0 < K; k0 += 8) {
        float4 av = *(const float4*)(Aptr + k0);
        As[a_c4 + 0][a_row] = av.x;
        As[a_c4 + 1][a_row] = av.y;
        As[a_c4 + 2][a_row] = av.z;
        As[a_c4 + 3][a_row] = av.w;
        float4 bv = *(const float4*)(Bptr + (size_t)k0 * Nn);
        *(float4*)&Bs[b_row][b_c4] = bv;
        __syncthreads();

#pragma unroll
        for (int kk = 0; kk < 8; kk++) {
            float ar[8], br[8];
            *(float4*)(ar + 0) = *(const float4*)&As[kk][ty * 8 + 0];
            *(float4*)(ar + 4) = *(const float4*)&As[kk][ty * 8 + 4];
            *(float4*)(br + 0) = *(const float4*)&Bs[kk][tx * 8 + 0];
            *(float4*)(br + 4) = *(const float4*)&Bs[kk][tx * 8 + 4];
#pragma unroll
            for (int i = 0; i < 8; i++)
#pragma unroll
                for (int j = 0; j < 8; j++)
                    acc[i][j] += ar[i] * br[j];
        }
        __syncthreads();
    }

    // Epilogue
#pragma unroll
    for (int i = 0; i < 8; i++) {
        const int row = rowBase + ty * 8 + i;
#pragma unroll
        for (int j = 0; j < 8; j++) {
            const int col = colBase + tx * 8 + j;
            float v = acc[i][j] + bias[col];
            if (MODE == 0) {
                const int b  = row >> 8;           // window
                const int n  = row & 255;          // token
                const int sel = col >> 9;          // 0:q 1:k 2:v
                const int h  = (col >> 5) & (NH - 1);
                const int hd = col & (HDIM - 1);
                const int off = ((b * NH + h) * NT + n) * HDIM + hd;
                if (sel == 0)      g_q[off] = v * QSCALE;
                else if (sel == 1) g_k[off] = v;
                else               g_v[off] = v;
            } else {
                C[(size_t)row * Nn + col] = v;
            }
        }
    }
}

// ---------------------------------------------------------------------------
// Attention: one block per (b,h). 256 threads, one query row each.
// Dynamic smem: Ks[256*32] | Vs[256*32] | biash[961] | rc[256] | cc[256]
// ---------------------------------------------------------------------------
#define SM_V_OFF   (NT * HDIM)            // 8192 floats
#define SM_B_OFF   (2 * NT * HDIM)        // 16384 floats
#define SM_RC_OFF  (SM_B_OFF + 961)       // 17345 floats (int region)
#define SM_CC_OFF  (SM_RC_OFF + NT)       // 17601
#define ATTN_SMEM_FLOATS (SM_CC_OFF + NT) // 17857
#define ATTN_SMEM_BYTES  (ATTN_SMEM_FLOATS * 4)

__global__ __launch_bounds__(256) void attn_kernel(const float* __restrict__ bias_table)
{
    extern __shared__ float smem[];
    float* Ks    = smem;
    float* Vs    = smem + SM_V_OFF;
    float* biash = smem + SM_B_OFF;
    int*   rc    = (int*)(smem + SM_RC_OFF);
    int*   cc    = (int*)(smem + SM_CC_OFF);

    const int bh = blockIdx.x;
    const int b  = bh >> 4;
    const int h  = bh & (NH - 1);
    const int t  = threadIdx.x;

    const float4* Kg4 = (const float4*)(g_k + (size_t)bh * NT * HDIM);
    const float4* Vg4 = (const float4*)(g_v + (size_t)bh * NT * HDIM);
    float4* Ks4 = (float4*)Ks;
    float4* Vs4 = (float4*)Vs;
#pragma unroll
    for (int i = t; i < NT * HDIM / 4; i += 256) {
        Ks4[i] = Kg4[i];
        Vs4[i] = Vg4[i];
    }
    for (int i = t; i < 961; i += 256) biash[i] = bias_table[i * NH + h];

    if (t == 0) {
        int r = 0, c = 0;
        for (int n = 0; n < NT; n++) {
            rc[n] = r; cc[n] = c;
            if (((r + c) & 1) == 0) {
                if (c == WSZ - 1) r++;
                else if (r == 0) c++;
                else { r--; c++; }
            } else {
                if (r == WSZ - 1) c++;
                else if (c == 0) r++;
                else { r++; c--; }
            }
        }
    }
    __syncthreads();

    // Load my query row (pre-scaled in GEMM epilogue)
    float q[HDIM];
    const float4* Qg4 = (const float4*)(g_q + ((size_t)bh * NT + t) * HDIM);
#pragma unroll
    for (int i = 0; i < HDIM / 4; i++) {
        float4 v = Qg4[i];
        q[4 * i + 0] = v.x; q[4 * i + 1] = v.y;
        q[4 * i + 2] = v.z; q[4 * i + 3] = v.w;
    }
    const int rn = rc[t], cn = cc[t];

    float mrun = -1e30f, l = 0.f;
    float acc[HDIM];
#pragma unroll
    for (int d = 0; d < HDIM; d++) acc[d] = 0.f;

    for (int m = 0; m < NT; m++) {
        const float* kr = &Ks[m * HDIM];
        float dot = 0.f;
#pragma unroll
        for (int d = 0; d < HDIM; d++) dot += q[d] * kr[d];
        const int dr = rn - rc[m] + (WSZ - 1);
        const int dc = cn - cc[m] + (WSZ - 1);
        const float s = dot + biash[dr * (2 * WSZ - 1) + dc];

        if (s > mrun) {
            const float corr = __expf(mrun - s);
            l *= corr;
#pragma unroll
            for (int d = 0; d < HDIM; d++) acc[d] *= corr;
            mrun = s;
        }
        const float p = __expf(s - mrun);
        l += p;
        const float* vr = &Vs[m * HDIM];
#pragma unroll
        for (int d = 0; d < HDIM; d++) acc[d] += p * vr[d];
    }

    const float inv = 1.f / l;
    float* outp = g_attn + ((size_t)(b * NT + t)) * DIMM + h * HDIM;
#pragma unroll
    for (int d = 0; d < HDIM; d++) outp[d] = acc[d] * inv;
}

// ---------------------------------------------------------------------------
// Launch
// ---------------------------------------------------------------------------
extern "C" void kernel_launch(void* const* d_in, const int* in_sizes, int n_in,
                              void* d_out, int out_size)
{
    const float* inputs     = (const float*)d_in[0];  // (256,256,512)
    const float* qkv_w      = (const float*)d_in[1];  // (512,1536)
    const float* qkv_b      = (const float*)d_in[2];  // (1536,)
    const float* proj_w     = (const float*)d_in[3];  // (512,512)
    const float* proj_b     = (const float*)d_in[4];  // (512,)
    const float* bias_table = (const float*)d_in[5];  // (961,16)
    float* out = (float*)d_out;                       // (256,256,512)

    // 1) QKV projection + scatter
    {
        dim3 grid(1536 / 128, (BW * NT) / 128);   // 12 x 512
        sgemm_kernel<0><<<grid, 256>>>(inputs, qkv_w, qkv_b, nullptr, DIMM, 3 * DIMM);
    }

    // 2) Attention
    {
        cudaFuncSetAttribute(attn_kernel, cudaFuncAttributeMaxDynamicSharedMemorySize,
                             ATTN_SMEM_BYTES);
        attn_kernel<<<BW * NH, 256, ATTN_SMEM_BYTES>>>(bias_table);
    }

    // 3) Output projection
    {
        dim3 grid(DIMM / 128, (BW * NT) / 128);   // 4 x 512
        sgemm_kernel<1><<<grid, 256>>>(nullptr, proj_w, proj_b, out, DIMM, DIMM);
    }
}